// round 1
// baseline (speedup 1.0000x reference)
#include <cuda_runtime.h>

// Problem constants
#define Nn 8
#define Cc 16
#define Ll 1024
#define Dd 7
#define Hh 16
#define SZ 112      // C*D = H*dh
#define PAD 8       // padded head_dim for float4 access

// Scratch: Q/K/V in [N, H, L, PAD] layout. Q pre-scaled by log2(e)/32.
__device__ float g_Q[Nn * Hh * Ll * PAD];
__device__ float g_K[Nn * Hh * Ll * PAD];
__device__ float g_V[Nn * Hh * Ll * PAD];

__device__ __forceinline__ float ex2f(float x) {
    float y;
    asm("ex2.approx.ftz.f32 %0, %1;" : "=f"(y) : "f"(x));
    return y;
}

// ---------------------------------------------------------------------------
// Projection: q/k/v = xf @ W^T + b, reshaped to [N, H, L, PAD].
// Grid: (256 row-blocks of 32, 3 matrices). 128 threads.
// SMEM: Wt[112][113] (transposed, padded) + As[32][113] + bias[112] = 64 KB.
// Thread (rr, oc): rr = tid>>4 picks 4 rows, oc = tid&15 picks one head (7 outs).
// ---------------------------------------------------------------------------
__global__ __launch_bounds__(128) void proj_kernel(
    const float* __restrict__ x,
    const float* __restrict__ Wq, const float* __restrict__ bq,
    const float* __restrict__ Wk, const float* __restrict__ bk,
    const float* __restrict__ Wv, const float* __restrict__ bv)
{
    extern __shared__ float sm[];
    float* Wt = sm;                    // [112][113]: Wt[i*113+o] = W[o][i]
    float* As = sm + 112 * 113;        // [32][113]
    float* bs = As + 32 * 113;         // [112]

    const int z = blockIdx.y;
    const float* W = (z == 0) ? Wq : ((z == 1) ? Wk : Wv);
    const float* b = (z == 0) ? bq : ((z == 1) ? bk : bv);
    float* dst     = (z == 0) ? g_Q : ((z == 1) ? g_K : g_V);
    // Fold softmax scale (1/sqrt(L)=1/32) and log2(e) into Q.
    const float scale = (z == 0) ? (1.4426950408889634f / 32.0f) : 1.0f;

    const int tid  = threadIdx.x;
    const int row0 = blockIdx.x * 32;

    // Stage W transposed (conflict-free reads later: 7*oc spans all banks).
    for (int e = tid; e < SZ * SZ; e += 128) {
        int o = e / SZ, i = e - o * SZ;
        Wt[i * 113 + o] = W[e];
    }
    // Stage xf tile: xf[row, i] = x[n, i/7, l, i%7]
    for (int e = tid; e < 32 * SZ; e += 128) {
        int r = e / SZ, i = e - r * SZ;
        int row = row0 + r;
        int n = row >> 10, l = row & 1023;
        int c = i / Dd, dd = i - c * Dd;
        As[r * 113 + i] = x[(((n * Cc + c) << 10) + l) * Dd + dd];
    }
    if (tid < SZ) bs[tid] = b[tid];
    __syncthreads();

    const int rr = tid >> 4;   // 0..7  -> rows rr*4 .. rr*4+3
    const int oc = tid & 15;   // head index 0..15 -> outputs oc*7 .. oc*7+6

    float acc[4][7];
#pragma unroll
    for (int k = 0; k < 4; ++k)
#pragma unroll
        for (int j = 0; j < 7; ++j) acc[k][j] = 0.0f;

#pragma unroll 4
    for (int i = 0; i < SZ; ++i) {
        float w[7];
#pragma unroll
        for (int j = 0; j < 7; ++j) w[j] = Wt[i * 113 + oc * 7 + j];
#pragma unroll
        for (int k = 0; k < 4; ++k) {
            float a = As[(rr * 4 + k) * 113 + i];
#pragma unroll
            for (int j = 0; j < 7; ++j) acc[k][j] = fmaf(a, w[j], acc[k][j]);
        }
    }

#pragma unroll
    for (int k = 0; k < 4; ++k) {
        int row = row0 + rr * 4 + k;
        int n = row >> 10, l = row & 1023;
        float* p = dst + (((n * Hh + oc) << 10) + l) * PAD;
#pragma unroll
        for (int j = 0; j < 7; ++j)
            p[j] = (acc[k][j] + bs[oc * 7 + j]) * scale;
    }
}

// ---------------------------------------------------------------------------
// Fused attention: one CTA per (n, h). K and V (1024 x PAD floats = 32 KB each)
// live in SMEM. 256 threads; thread owns rows {tid, tid+256, tid+512, tid+768}.
// Single-pass softmax (no max subtraction: |score| <~ 2 so exp is safe).
// Q is pre-scaled by log2(e)/32, so weight = ex2(q.k).
// ---------------------------------------------------------------------------
__global__ __launch_bounds__(256) void attn_kernel(float* __restrict__ out)
{
    extern __shared__ float sm[];
    float4* K4 = (float4*)sm;          // 2048 float4
    float4* V4 = K4 + 2048;            // 2048 float4

    const int bh  = blockIdx.x;        // n*16 + h
    const int tid = threadIdx.x;

    const float4* gK4 = (const float4*)g_K + bh * 2048;
    const float4* gV4 = (const float4*)g_V + bh * 2048;
    for (int e = tid; e < 2048; e += 256) {
        K4[e] = gK4[e];
        V4[e] = gV4[e];
    }

    float q[4][7];
#pragma unroll
    for (int k = 0; k < 4; ++k) {
        const float* qp = g_Q + (bh * Ll + tid + 256 * k) * PAD;
#pragma unroll
        for (int j = 0; j < 7; ++j) q[k][j] = qp[j];
    }
    __syncthreads();

    float ssum[4] = {0.f, 0.f, 0.f, 0.f};
    float acc[4][7];
#pragma unroll
    for (int k = 0; k < 4; ++k)
#pragma unroll
        for (int j = 0; j < 7; ++j) acc[k][j] = 0.0f;

#pragma unroll 2
    for (int jj = 0; jj < Ll; ++jj) {
        float4 ka = K4[2 * jj], kb = K4[2 * jj + 1];
        float4 va = V4[2 * jj], vb = V4[2 * jj + 1];
#pragma unroll
        for (int k = 0; k < 4; ++k) {
            float s = q[k][0] * ka.x;
            s = fmaf(q[k][1], ka.y, s);
            s = fmaf(q[k][2], ka.z, s);
            s = fmaf(q[k][3], ka.w, s);
            s = fmaf(q[k][4], kb.x, s);
            s = fmaf(q[k][5], kb.y, s);
            s = fmaf(q[k][6], kb.z, s);
            float e = ex2f(s);
            ssum[k] += e;
            acc[k][0] = fmaf(e, va.x, acc[k][0]);
            acc[k][1] = fmaf(e, va.y, acc[k][1]);
            acc[k][2] = fmaf(e, va.z, acc[k][2]);
            acc[k][3] = fmaf(e, va.w, acc[k][3]);
            acc[k][4] = fmaf(e, vb.x, acc[k][4]);
            acc[k][5] = fmaf(e, vb.y, acc[k][5]);
            acc[k][6] = fmaf(e, vb.z, acc[k][6]);
        }
    }

#pragma unroll
    for (int k = 0; k < 4; ++k) {
        int row = tid + 256 * k;
        float inv = 1.0f / ssum[k];
        float* p = out + (bh * Ll + row) * Dd;
#pragma unroll
        for (int j = 0; j < 7; ++j) p[j] = acc[k][j] * inv;
    }
}

extern "C" void kernel_launch(void* const* d_in, const int* in_sizes, int n_in,
                              void* d_out, int out_size)
{
    const float* x  = (const float*)d_in[0];
    const float* Wq = (const float*)d_in[1];
    const float* bq = (const float*)d_in[2];
    const float* Wk = (const float*)d_in[3];
    const float* bk = (const float*)d_in[4];
    const float* Wv = (const float*)d_in[5];
    const float* bv = (const float*)d_in[6];

    // 64 KB dynamic SMEM for both kernels (idempotent; safe during capture).
    cudaFuncSetAttribute(proj_kernel, cudaFuncAttributeMaxDynamicSharedMemorySize, 65536);
    cudaFuncSetAttribute(attn_kernel, cudaFuncAttributeMaxDynamicSharedMemorySize, 65536);

    proj_kernel<<<dim3(256, 3, 1), 128, 65536>>>(x, Wq, bq, Wk, bk, Wv, bv);
    attn_kernel<<<Nn * Hh, 256, 65536>>>((float*)d_out);
}